// round 14
// baseline (speedup 1.0000x reference)
#include <cuda_runtime.h>
#include <cstdint>

// Depthwise 3D conv 3x3x3, SAME, stride 1.
// x: (4,16,112,112,64) f32 NDHWC; w: (3,3,3,1,64) f32.
//
// Thread: 2 channels (f32x2), 8 w-outputs, 2 h-rows. Per-row schedule:
// batched rv[10] LDG burst -> weight LDG (L1-resident) -> 48 packed FMA.
// Interior/edge block split; __launch_bounds__(64,14).
// R14 vs R10: output stores use st.global.cs (evict-first streaming) so the
// 205MB write stream stops evicting the input halo from L2 (write data is
// never re-read). Theory: frees L2 for d/h halo reuse -> fewer DRAM reads.

#define N_  4
#define D_  16
#define H_  112
#define W_  112
#define C_  64
#define WPT 8
#define CS  (C_ / 2)   // 32 ull per spatial position

typedef unsigned long long ull;

__device__ __forceinline__ ull ffma2(ull a, ull b, ull c) {
    ull d;
    asm("fma.rn.f32x2 %0, %1, %2, %3;" : "=l"(d) : "l"(a), "l"(b), "l"(c));
    return d;
}

__device__ __forceinline__ void stcs(ull* p, ull v) {
    asm volatile("st.global.cs.b64 [%0], %1;" :: "l"(p), "l"(v) : "memory");
}

template <bool INT>
__device__ __forceinline__ void conv_body(
    const ull* __restrict__ xp, const ull* __restrict__ swp,
    ull* __restrict__ out, int n, int d, int h0, int w0, int tx) {

    const bool wlo = INT || (w0 > 0);
    const bool whi = INT || (w0 + WPT < W_);

    ull acc0[WPT], acc1[WPT];
#pragma unroll
    for (int i = 0; i < WPT; i++) { acc0[i] = 0ull; acc1[i] = 0ull; }

#pragma unroll
    for (int kd = 0; kd < 3; kd++) {
        const int zd = d + kd - 1;
        if (!INT && (unsigned)zd >= D_) continue;

        // pointer to (n, zd, h0-1, w0, tx); advances one h-row per r
        const ull* rowp =
            xp + ((((n * D_ + zd) * H_ + (h0 - 1)) * W_ + w0) * CS + tx);

        // weight rotation: wa = taps (kd, kh=r), wb = (kd, kh=r-1)
        ull wa0 = 0, wa1 = 0, wa2 = 0;
        ull wb0, wb1, wb2;

#pragma unroll
        for (int r = 0; r < 4; r++) {          // zh = h0-1 .. h0+2
            const int zh = h0 - 1 + r;
            const bool rowOk = INT || ((unsigned)zh < H_);

            ull rv[WPT + 2];
            if (rowOk) {
                // batched row preload: 10 LDGs, immediate offsets
                rv[0] = wlo ? rowp[-CS] : 0ull;
#pragma unroll
                for (int j = 0; j < WPT; j++)
                    rv[j + 1] = rowp[j * CS];
                rv[WPT + 1] = whi ? rowp[WPT * CS] : 0ull;
            }

            // weight rotate + fetch (drains under LDG latency)
            wb0 = wa0; wb1 = wa1; wb2 = wa2;
            if (r < 3) {
                const int base = (kd * 9 + r * 3) * CS + tx;
                wa0 = swp[base];
                wa1 = swp[base + CS];
                wa2 = swp[base + 2 * CS];
            }

            if (rowOk) {
                // register-only FMA burst
#pragma unroll
                for (int i = 0; i < WPT; i++) {
                    if (r <= 2) {                          // output h0, kh=r
                        acc0[i] = ffma2(rv[i],     wa0, acc0[i]);
                        acc0[i] = ffma2(rv[i + 1], wa1, acc0[i]);
                        acc0[i] = ffma2(rv[i + 2], wa2, acc0[i]);
                    }
                    if (r >= 1) {                          // output h0+1, kh=r-1
                        acc1[i] = ffma2(rv[i],     wb0, acc1[i]);
                        acc1[i] = ffma2(rv[i + 1], wb1, acc1[i]);
                        acc1[i] = ffma2(rv[i + 2], wb2, acc1[i]);
                    }
                }
            }
            rowp += W_ * CS;
        }
    }

    ull* op = out + ((((n * D_ + d) * H_ + h0) * W_ + w0) * CS + tx);
#pragma unroll
    for (int i = 0; i < WPT; i++) {
        stcs(op + i * CS, acc0[i]);
        stcs(op + W_ * CS + i * CS, acc1[i]);
    }
}

__global__ void __launch_bounds__(64, 14)
dwconv3d_kernel(const float* __restrict__ x,
                const float* __restrict__ wgt,
                float* __restrict__ out) {
    const ull* __restrict__ swp = reinterpret_cast<const ull*>(wgt);
    const ull* __restrict__ xp  = reinterpret_cast<const ull*>(x);
    ull* __restrict__ op        = reinterpret_cast<ull*>(out);

    const int tx = threadIdx.x;                       // channel pair 0..31
    const int h0 = blockIdx.y * 4 + threadIdx.y * 2;  // even rows 0..110
    const int w0 = blockIdx.x * WPT;                  // 0..104
    const int nd = blockIdx.z;
    const int n  = nd >> 4;
    const int d  = nd & 15;

    // Block-uniform interior test: no d/h/w halo clamping anywhere in block.
    const bool interior =
        (d >= 1) && (d <= 14) &&
        (blockIdx.y >= 1) && (blockIdx.y <= (H_ / 4) - 2) &&
        (blockIdx.x >= 1) && (blockIdx.x <= (W_ / WPT) - 2);

    if (interior)
        conv_body<true>(xp, swp, op, n, d, h0, w0, tx);
    else
        conv_body<false>(xp, swp, op, n, d, h0, w0, tx);
}

extern "C" void kernel_launch(void* const* d_in, const int* in_sizes, int n_in,
                              void* d_out, int out_size) {
    const float* x = (const float*)d_in[0];
    const float* w = (const float*)d_in[1];
    float* o = (float*)d_out;

    dim3 block(32, 2, 1);                        // 64 threads
    dim3 grid(W_ / WPT, H_ / 4, N_ * D_);        // 14 x 28 x 64
    dwconv3d_kernel<<<grid, block>>>(x, w, o);
}

// round 15
// speedup vs baseline: 1.0259x; 1.0259x over previous
#include <cuda_runtime.h>
#include <cstdint>

// Depthwise 3D conv 3x3x3, SAME, stride 1.
// x: (4,16,112,112,64) f32 NDHWC; w: (3,3,3,1,64) f32.
//
// Thread: 2 channels (f32x2), 8 w-outputs, 2 h-rows.
// Interior blocks: guard-free double-buffered row pipeline (row r+1's 10-LDG
// burst issues before row r's 48 packed FMAs). Edge blocks: guarded single
// buffer. Plain STG stores (st.cs regressed in R14).
// R15 vs R12: __launch_bounds__(64,12) — cap 85 keeps the 78-reg pipeline
// intact while raising blocks/SM 11->12 (occ 34.4% -> 37.5%).

#define N_  4
#define D_  16
#define H_  112
#define W_  112
#define C_  64
#define WPT 8
#define CS  (C_ / 2)   // 32 ull per spatial position
#define ROWSTEP (W_ * CS)

typedef unsigned long long ull;

__device__ __forceinline__ ull ffma2(ull a, ull b, ull c) {
    ull d;
    asm("fma.rn.f32x2 %0, %1, %2, %3;" : "=l"(d) : "l"(a), "l"(b), "l"(c));
    return d;
}

// ---------------- interior: guard-free, double-buffered row pipeline --------
__device__ __forceinline__ void conv_interior(
    const ull* __restrict__ xp, const ull* __restrict__ swp,
    ull* __restrict__ out, int n, int d, int h0, int w0, int tx) {

    ull acc0[WPT], acc1[WPT];
#pragma unroll
    for (int i = 0; i < WPT; i++) { acc0[i] = 0ull; acc1[i] = 0ull; }

#pragma unroll
    for (int kd = 0; kd < 3; kd++) {
        const int zd = d + kd - 1;                    // always in [0,15]
        const ull* rowp =
            xp + ((((n * D_ + zd) * H_ + (h0 - 1)) * W_ + w0) * CS + tx);

        ull wa0 = 0, wa1 = 0, wa2 = 0;
        ull wb0, wb1, wb2;

        ull buf[2][WPT + 2];

        // prime: row r=0 (zh = h0-1), 10 unconditional LDGs
#pragma unroll
        for (int j = 0; j < WPT + 2; j++)
            buf[0][j] = rowp[(j - 1) * CS];

#pragma unroll
        for (int r = 0; r < 4; r++) {                 // zh = h0-1+r
            // prefetch next row into the other buffer BEFORE this row's FMAs
            if (r < 3) {
                const ull* np = rowp + ROWSTEP;
#pragma unroll
                for (int j = 0; j < WPT + 2; j++)
                    buf[(r + 1) & 1][j] = np[(j - 1) * CS];
            }

            // weight rotate + fetch (drains under prefetch latency)
            wb0 = wa0; wb1 = wa1; wb2 = wa2;
            if (r < 3) {
                const int base = (kd * 9 + r * 3) * CS + tx;
                wa0 = swp[base];
                wa1 = swp[base + CS];
                wa2 = swp[base + 2 * CS];
            }

            const ull* rv = buf[r & 1];
#pragma unroll
            for (int i = 0; i < WPT; i++) {
                if (r <= 2) {                          // output h0, kh=r
                    acc0[i] = ffma2(rv[i],     wa0, acc0[i]);
                    acc0[i] = ffma2(rv[i + 1], wa1, acc0[i]);
                    acc0[i] = ffma2(rv[i + 2], wa2, acc0[i]);
                }
                if (r >= 1) {                          // output h0+1, kh=r-1
                    acc1[i] = ffma2(rv[i],     wb0, acc1[i]);
                    acc1[i] = ffma2(rv[i + 1], wb1, acc1[i]);
                    acc1[i] = ffma2(rv[i + 2], wb2, acc1[i]);
                }
            }
            rowp += ROWSTEP;
        }
    }

    ull* __restrict__ op =
        out + ((((n * D_ + d) * H_ + h0) * W_ + w0) * CS + tx);
#pragma unroll
    for (int i = 0; i < WPT; i++) {
        op[i * CS] = acc0[i];
        op[ROWSTEP + i * CS] = acc1[i];
    }
}

// ---------------- edge: guarded single-buffer ------------------------------
__device__ __forceinline__ void conv_edge(
    const ull* __restrict__ xp, const ull* __restrict__ swp,
    ull* __restrict__ out, int n, int d, int h0, int w0, int tx) {

    const bool wlo = (w0 > 0);
    const bool whi = (w0 + WPT < W_);

    ull acc0[WPT], acc1[WPT];
#pragma unroll
    for (int i = 0; i < WPT; i++) { acc0[i] = 0ull; acc1[i] = 0ull; }

#pragma unroll
    for (int kd = 0; kd < 3; kd++) {
        const int zd = d + kd - 1;
        if ((unsigned)zd >= D_) continue;

        const ull* rowp =
            xp + ((((n * D_ + zd) * H_ + (h0 - 1)) * W_ + w0) * CS + tx);

        ull wa0 = 0, wa1 = 0, wa2 = 0;
        ull wb0, wb1, wb2;

#pragma unroll
        for (int r = 0; r < 4; r++) {
            const int zh = h0 - 1 + r;
            const bool rowOk = ((unsigned)zh < H_);

            ull rv[WPT + 2];
            if (rowOk) {
                rv[0] = wlo ? rowp[-CS] : 0ull;
#pragma unroll
                for (int j = 0; j < WPT; j++)
                    rv[j + 1] = rowp[j * CS];
                rv[WPT + 1] = whi ? rowp[WPT * CS] : 0ull;
            }

            wb0 = wa0; wb1 = wa1; wb2 = wa2;
            if (r < 3) {
                const int base = (kd * 9 + r * 3) * CS + tx;
                wa0 = swp[base];
                wa1 = swp[base + CS];
                wa2 = swp[base + 2 * CS];
            }

            if (rowOk) {
#pragma unroll
                for (int i = 0; i < WPT; i++) {
                    if (r <= 2) {
                        acc0[i] = ffma2(rv[i],     wa0, acc0[i]);
                        acc0[i] = ffma2(rv[i + 1], wa1, acc0[i]);
                        acc0[i] = ffma2(rv[i + 2], wa2, acc0[i]);
                    }
                    if (r >= 1) {
                        acc1[i] = ffma2(rv[i],     wb0, acc1[i]);
                        acc1[i] = ffma2(rv[i + 1], wb1, acc1[i]);
                        acc1[i] = ffma2(rv[i + 2], wb2, acc1[i]);
                    }
                }
            }
            rowp += ROWSTEP;
        }
    }

    ull* __restrict__ op =
        out + ((((n * D_ + d) * H_ + h0) * W_ + w0) * CS + tx);
#pragma unroll
    for (int i = 0; i < WPT; i++) {
        op[i * CS] = acc0[i];
        op[ROWSTEP + i * CS] = acc1[i];
    }
}

__global__ void __launch_bounds__(64, 12)
dwconv3d_kernel(const float* __restrict__ x,
                const float* __restrict__ wgt,
                float* __restrict__ out) {
    const ull* __restrict__ swp = reinterpret_cast<const ull*>(wgt);
    const ull* __restrict__ xp  = reinterpret_cast<const ull*>(x);
    ull* __restrict__ op        = reinterpret_cast<ull*>(out);

    const int tx = threadIdx.x;                       // channel pair 0..31
    const int h0 = blockIdx.y * 4 + threadIdx.y * 2;  // even rows 0..110
    const int w0 = blockIdx.x * WPT;                  // 0..104
    const int nd = blockIdx.z;
    const int n  = nd >> 4;
    const int d  = nd & 15;

    const bool interior =
        (d >= 1) && (d <= 14) &&
        (blockIdx.y >= 1) && (blockIdx.y <= (H_ / 4) - 2) &&
        (blockIdx.x >= 1) && (blockIdx.x <= (W_ / WPT) - 2);

    if (interior)
        conv_interior(xp, swp, op, n, d, h0, w0, tx);
    else
        conv_edge(xp, swp, op, n, d, h0, w0, tx);
}

extern "C" void kernel_launch(void* const* d_in, const int* in_sizes, int n_in,
                              void* d_out, int out_size) {
    const float* x = (const float*)d_in[0];
    const float* w = (const float*)d_in[1];
    float* o = (float*)d_out;

    dim3 block(32, 2, 1);                        // 64 threads
    dim3 grid(W_ / WPT, H_ / 4, N_ * D_);        // 14 x 28 x 64
    dwconv3d_kernel<<<grid, block>>>(x, w, o);
}